// round 13
// baseline (speedup 1.0000x reference)
#include <cuda_runtime.h>
#include <cuda_bf16.h>
#include <cstdint>

// Problem constants
#define BB 3
#define HH 256
#define WW 256
#define CC 16
#define NB 4
#define COUT 64
#define SN 64
#define EPS 1e-3f

// Scratch (__device__ globals: allocation-free rule)
__device__ float g_x1[BB * HH * WW * COUT];      // conv1 output (BN+ReLU, fp32)
__device__ float g_bf[BB * HH * WW * COUT];      // conv2 out -> softmax/mask in place
__device__ float g_ratio[BB * SN * SN * CC * NB];
__device__ float g_B1[9 * 64 * 16];              // W1 transposed [t][oc][ic], tf32-rounded
__device__ float g_B2[9 * 64 * 64];              // W2 transposed [t][oc][ic], tf32-rounded
__device__ float g_dnc[BB * 65 * 65 * CC * NB];  // 4x4 cell sums of b
__device__ float g_kpc[BB * 65 * 65 * CC * NB];  // 4x4 cell sums of pet*b

__device__ __forceinline__ uint32_t f2tf32(float f) {
    uint32_t r; asm("cvt.rna.tf32.f32 %0, %1;" : "=r"(r) : "f"(f)); return r;
}

__device__ __forceinline__ void mma_tf32(float& c0, float& c1, float& c2, float& c3,
                                         uint32_t a0, uint32_t a1, uint32_t a2, uint32_t a3,
                                         uint32_t b0, uint32_t b1) {
    asm volatile(
        "mma.sync.aligned.m16n8k8.row.col.f32.tf32.tf32.f32 "
        "{%0,%1,%2,%3}, {%4,%5,%6,%7}, {%8,%9}, {%0,%1,%2,%3};\n"
        : "+f"(c0), "+f"(c1), "+f"(c2), "+f"(c3)
        : "r"(a0), "r"(a1), "r"(a2), "r"(a3), "r"(b0), "r"(b1));
}

__device__ __forceinline__ float4 softmax_mask4(float4 v) {
    float mx = fmaxf(fmaxf(v.x, v.y), fmaxf(v.z, v.w));
    float ex = __expf(v.x - mx);
    float ey = __expf(v.y - mx);
    float ez = __expf(v.z - mx);
    float ew = __expf(v.w - mx);
    float inv = 1.f / (ex + ey + ez + ew);
    ex *= inv; ey *= inv; ez *= inv; ew *= inv;
    float4 o;
    o.x = ex > 1e-5f ? ex : 0.f;
    o.y = ey > 1e-5f ? ey : 0.f;
    o.z = ez > 1e-5f ? ez : 0.f;
    o.w = ew > 1e-5f ? ew : 0.f;
    return o;
}

// ---------------------------------------------------------------------------
// Weight prep: W [3,3,CIN,64] (HWIO) -> B [9][64][CIN] tf32-rounded fp32
// ---------------------------------------------------------------------------
__global__ void wprep_kernel(const float* __restrict__ W1, const float* __restrict__ W2,
                             float* __restrict__ B1, float* __restrict__ B2)
{
    int i = blockIdx.x * blockDim.x + threadIdx.x;
    if (i < 9 * 64 * 16) {
        int ic = i & 15, oc = (i >> 4) & 63, t = i >> 10;
        uint32_t v = f2tf32(W1[(t * 16 + ic) * 64 + oc]);
        B1[(t * 64 + oc) * 16 + ic] = __uint_as_float(v);
    }
    if (i < 9 * 64 * 64) {
        int ic = i & 63, oc = (i >> 6) & 63, t = i >> 12;
        uint32_t v = f2tf32(W2[(t * 64 + ic) * 64 + oc]);
        B2[(t * 64 + oc) * 64 + ic] = __uint_as_float(v);
    }
}

// ---------------------------------------------------------------------------
// Implicit-GEMM 3x3 SAME conv via mma.sync tf32 + folded BN (round-4 shape,
// untouched). CTA = one image row: 256 px x 64 oc; 4 warps, M=64 x N=64.
// ---------------------------------------------------------------------------
#define ASTR 20
template <int CIN, int DO_RELU>
__global__ __launch_bounds__(128) void conv_mma(
    const float* __restrict__ in, const float* __restrict__ Bw,
    const float* __restrict__ bias, const float* __restrict__ gam,
    const float* __restrict__ bet, const float* __restrict__ mu,
    const float* __restrict__ var, float* __restrict__ out)
{
    __shared__ __align__(16) float s_a[258 * ASTR];
    __shared__ __align__(16) float s_b[3 * 64 * ASTR];
    __shared__ float s_sc[64], s_sh[64];

    const int tid  = threadIdx.x;
    const int lane = tid & 31;
    const int warp = tid >> 5;
    const int lg   = lane >> 2;
    const int lt   = lane & 3;
    const int wp0  = warp * 64;

    const int y  = blockIdx.x;
    const int bb = blockIdx.y;

    if (tid < 64) {
        float sc = gam[tid] * rsqrtf(var[tid] + EPS);
        s_sc[tid] = sc;
        s_sh[tid] = (bias[tid] - mu[tid]) * sc + bet[tid];
    }

    float acc[4][8][4];
#pragma unroll
    for (int mt = 0; mt < 4; ++mt)
#pragma unroll
        for (int n = 0; n < 8; ++n)
#pragma unroll
            for (int c = 0; c < 4; ++c) acc[mt][n][c] = 0.f;

    for (int ky = 0; ky < 3; ++ky) {
        const int gy = y + ky - 1;
        const bool row_ok = (unsigned)gy < (unsigned)HH;
        const float* rowp = in + ((size_t)(bb * HH + gy) * WW) * CIN;

        for (int ic0 = 0; ic0 < CIN; ic0 += 16) {
            __syncthreads();
            for (int idx = tid; idx < 258 * 4; idx += 128) {
                int c4 = idx & 3;
                int p  = idx >> 2;
                int gx = p - 1;
                uint4 v = make_uint4(0u, 0u, 0u, 0u);
                if (row_ok && (unsigned)gx < (unsigned)WW) {
                    float4 f = *(const float4*)(rowp + gx * CIN + ic0 + c4 * 4);
                    v.x = f2tf32(f.x); v.y = f2tf32(f.y);
                    v.z = f2tf32(f.z); v.w = f2tf32(f.w);
                }
                *(uint4*)&s_a[p * ASTR + c4 * 4] = v;
            }
            for (int idx = tid; idx < 3 * 64 * 4; idx += 128) {
                int c4  = idx & 3;
                int oc  = (idx >> 2) & 63;
                int tap = idx >> 8;
                float4 f = *(const float4*)(Bw + ((ky * 3 + tap) * 64 + oc) * CIN + ic0 + c4 * 4);
                *(float4*)&s_b[(tap * 64 + oc) * ASTR + c4 * 4] = f;
            }
            __syncthreads();

#pragma unroll
            for (int kx = 0; kx < 3; ++kx) {
#pragma unroll
                for (int g = 0; g < 2; ++g) {
                    const int icw = g * 8 + lt;
                    uint32_t b0[8], b1[8];
#pragma unroll
                    for (int n = 0; n < 8; ++n) {
                        const float* bp = &s_b[(kx * 64 + n * 8 + lg) * ASTR + icw];
                        b0[n] = __float_as_uint(bp[0]);
                        b1[n] = __float_as_uint(bp[4]);
                    }
#pragma unroll
                    for (int mt = 0; mt < 4; ++mt) {
                        const int r0 = wp0 + mt * 16 + kx + lg;
                        const float* ap0 = &s_a[r0 * ASTR + icw];
                        const float* ap1 = ap0 + 8 * ASTR;
                        uint32_t a0 = __float_as_uint(ap0[0]);
                        uint32_t a1 = __float_as_uint(ap1[0]);
                        uint32_t a2 = __float_as_uint(ap0[4]);
                        uint32_t a3 = __float_as_uint(ap1[4]);
#pragma unroll
                        for (int n = 0; n < 8; ++n)
                            mma_tf32(acc[mt][n][0], acc[mt][n][1], acc[mt][n][2], acc[mt][n][3],
                                     a0, a1, a2, a3, b0[n], b1[n]);
                    }
                }
            }
        }
    }

    // ---- epilogue: BN (+ReLU), store fp32 NHWC
    float* ob = out + ((size_t)(bb * HH + y) * WW) * COUT;
#pragma unroll
    for (int mt = 0; mt < 4; ++mt) {
        int prow = wp0 + mt * 16 + lg;
#pragma unroll
        for (int n = 0; n < 8; ++n) {
            int col = n * 8 + lt * 2;
            float sc0 = s_sc[col], sc1 = s_sc[col + 1];
            float sh0 = s_sh[col], sh1 = s_sh[col + 1];
            float v0 = acc[mt][n][0] * sc0 + sh0;
            float v1 = acc[mt][n][1] * sc1 + sh1;
            float v2 = acc[mt][n][2] * sc0 + sh0;
            float v3 = acc[mt][n][3] * sc1 + sh1;
            if (DO_RELU) {
                v0 = fmaxf(v0, 0.f); v1 = fmaxf(v1, 0.f);
                v2 = fmaxf(v2, 0.f); v3 = fmaxf(v3, 0.f);
            }
            *(float2*)(ob + (size_t)prow * COUT + col)       = make_float2(v0, v1);
            *(float2*)(ob + (size_t)(prow + 8) * COUT + col) = make_float2(v2, v3);
        }
    }
}

// ---------------------------------------------------------------------------
// Softmax over NB=4 + mask, in place. ILP=2: each thread owns two
// independent float4 groups to overlap the exp/div dependency chains.
// ---------------------------------------------------------------------------
__global__ void softmax_mask_kernel(float* __restrict__ bf, int n4)
{
    int i0 = (blockIdx.x * blockDim.x + threadIdx.x) * 2;
    if (i0 >= n4) return;
    float4* p = (float4*)bf;
    float4 a = p[i0];
    float4 b = (i0 + 1 < n4) ? p[i0 + 1] : make_float4(0.f, 0.f, 0.f, 0.f);
    float4 oa = softmax_mask4(a);
    float4 ob = softmax_mask4(b);
    p[i0] = oa;
    if (i0 + 1 < n4) p[i0 + 1] = ob;
}

// ---------------------------------------------------------------------------
// Cell sums: non-overlapping 4x4 blocks over masked-softmax bf.
// Cell u covers gx in [4u-2, 4u+2), u = 0..64, edges clipped.
// ---------------------------------------------------------------------------
__global__ void cell_kernel(const float* __restrict__ bf, const float* __restrict__ pet,
                            float* __restrict__ dnc, float* __restrict__ kpc)
{
    int idx = blockIdx.x * blockDim.x + threadIdx.x;
    if (idx >= BB * 65 * 65 * CC) return;
    int cc = idx & 15;
    int t  = idx >> 4;
    int v  = t % 65;
    int t2 = t / 65;
    int u  = t2 % 65;
    int b  = t2 / 65;

    float4 dn = make_float4(0.f, 0.f, 0.f, 0.f);
    float4 kp = make_float4(0.f, 0.f, 0.f, 0.f);
    int gx0 = u * 4 - 2, gy0 = v * 4 - 2;
#pragma unroll
    for (int dx = 0; dx < 4; ++dx) {
        int gx = gx0 + dx;
        if ((unsigned)gx >= (unsigned)HH) continue;
#pragma unroll
        for (int dy = 0; dy < 4; ++dy) {
            int gy = gy0 + dy;
            if ((unsigned)gy >= (unsigned)WW) continue;
            int pix = (b * HH + gx) * WW + gy;
            float4 bv = *(const float4*)&bf[pix * COUT + cc * 4];
            float  pv = pet[pix * CC + cc];
            dn.x += bv.x; dn.y += bv.y; dn.z += bv.z; dn.w += bv.w;
            kp.x = fmaf(pv, bv.x, kp.x);
            kp.y = fmaf(pv, bv.y, kp.y);
            kp.z = fmaf(pv, bv.z, kp.z);
            kp.w = fmaf(pv, bv.w, kp.w);
        }
    }
    ((float4*)dnc)[idx] = dn;
    ((float4*)kpc)[idx] = kp;
}

// ---------------------------------------------------------------------------
// Combine 2x2 cells -> per-patch ratio with divide_no_nan.
// ---------------------------------------------------------------------------
__global__ void combine_kernel(const float* __restrict__ dnc, const float* __restrict__ kpc,
                               float* __restrict__ ratio)
{
    int idx = blockIdx.x * blockDim.x + threadIdx.x;
    if (idx >= BB * SN * SN * CC) return;
    int cc = idx & 15;
    int t  = idx >> 4;
    int m  = t & 63;
    int t2 = t >> 6;
    int n  = t2 & 63;
    int b  = t2 >> 6;

    float4 dn = make_float4(0.f, 0.f, 0.f, 0.f);
    float4 kp = make_float4(0.f, 0.f, 0.f, 0.f);
#pragma unroll
    for (int du = 0; du < 2; ++du)
#pragma unroll
        for (int dv = 0; dv < 2; ++dv) {
            int ci = (((b * 65 + n + du) * 65) + m + dv) * CC + cc;
            float4 d = ((const float4*)dnc)[ci];
            float4 k = ((const float4*)kpc)[ci];
            dn.x += d.x; dn.y += d.y; dn.z += d.z; dn.w += d.w;
            kp.x += k.x; kp.y += k.y; kp.z += k.z; kp.w += k.w;
        }
    float4 r;
    r.x = dn.x != 0.f ? kp.x / dn.x : 0.f;
    r.y = dn.y != 0.f ? kp.y / dn.y : 0.f;
    r.z = dn.z != 0.f ? kp.z / dn.z : 0.f;
    r.w = dn.w != 0.f ? kp.w / dn.w : 0.f;
    ((float4*)ratio)[idx] = r;
}

// ---------------------------------------------------------------------------
// Final gather over masked-softmax bf. Interior (2<=X<254, 2<=Y<254): all
// four (i,j) terms hit the SAME bf pixel (X,Y) -> one bf load, dot with the
// SUM of the four ratio vectors. Boundary: general wrapped path.
// ---------------------------------------------------------------------------
__global__ void out_kernel(const float* __restrict__ bf,
                           const float* __restrict__ ratio,
                           float* __restrict__ out, int ntot)
{
    int idx = blockIdx.x * blockDim.x + threadIdx.x;
    if (idx >= ntot) return;
    int cc  = idx & 15;
    int pix = idx >> 4;
    int Y = pix & 255;
    int t = pix >> 8;
    int X = t & 255;
    int b = t >> 8;

    float s;
    if (X >= 2 && X < 254 && Y >= 2 && Y < 254) {
        int n0 = ((X + 2) >> 3) * 2;
        int n1 = ((X - 2) >> 3) * 2 + 1;
        int m0 = ((Y + 2) >> 3) * 2;
        int m1 = ((Y - 2) >> 3) * 2 + 1;
        const float4* rb = (const float4*)ratio;
        int base = (b * SN) * SN * CC;
        float4 r00 = rb[base + (n0 * SN + m0) * CC + cc];
        float4 r01 = rb[base + (n0 * SN + m1) * CC + cc];
        float4 r10 = rb[base + (n1 * SN + m0) * CC + cc];
        float4 r11 = rb[base + (n1 * SN + m1) * CC + cc];
        float4 rs;
        rs.x = (r00.x + r01.x) + (r10.x + r11.x);
        rs.y = (r00.y + r01.y) + (r10.y + r11.y);
        rs.z = (r00.z + r01.z) + (r10.z + r11.z);
        rs.w = (r00.w + r01.w) + (r10.w + r11.w);
        float4 bv = *(const float4*)&bf[((b * HH + X) * WW + Y) * COUT + cc * 4];
        s = bv.x * rs.x + bv.y * rs.y + bv.z * rs.z + bv.w * rs.w;
    } else {
        s = 0.f;
#pragma unroll
        for (int j = 0; j < 2; ++j) {
            int Yp = (Y - (j ? 2 : -2)) & 255;
            int m  = (Yp >> 3) * 2 + j;
            int gy = Yp + 4 * j - 2;
#pragma unroll
            for (int i = 0; i < 2; ++i) {
                int Xp = (X - (i ? 2 : -2)) & 255;
                int n  = (Xp >> 3) * 2 + i;
                int gx = Xp + 4 * i - 2;
                if ((unsigned)gx < (unsigned)HH && (unsigned)gy < (unsigned)WW) {
                    int pp = (b * HH + gx) * WW + gy;
                    float4 bv = *(const float4*)&bf[pp * COUT + cc * 4];
                    float4 rv = *(const float4*)&ratio[(((b * SN + n) * SN + m) * CC + cc) * 4];
                    s += bv.x * rv.x + bv.y * rv.y + bv.z * rv.z + bv.w * rv.w;
                }
            }
        }
    }
    out[idx] = s * 0.25f;
}

// ---------------------------------------------------------------------------
extern "C" void kernel_launch(void* const* d_in, const int* in_sizes, int n_in,
                              void* d_out, int out_size)
{
    const float* mr  = (const float*)d_in[0];
    const float* pet = (const float*)d_in[1];
    const float* W1  = (const float*)d_in[2];
    const float* b1  = (const float*)d_in[3];
    const float* g1  = (const float*)d_in[4];
    const float* be1 = (const float*)d_in[5];
    const float* mu1 = (const float*)d_in[6];
    const float* v1  = (const float*)d_in[7];
    const float* W2  = (const float*)d_in[8];
    const float* b2  = (const float*)d_in[9];
    const float* g2  = (const float*)d_in[10];
    const float* be2 = (const float*)d_in[11];
    const float* mu2 = (const float*)d_in[12];
    const float* v2  = (const float*)d_in[13];
    float* outp = (float*)d_out;

    float *x1p, *bfp, *ratp, *B1p, *B2p, *dncp, *kpcp;
    cudaGetSymbolAddress((void**)&x1p, g_x1);
    cudaGetSymbolAddress((void**)&bfp, g_bf);
    cudaGetSymbolAddress((void**)&ratp, g_ratio);
    cudaGetSymbolAddress((void**)&B1p, g_B1);
    cudaGetSymbolAddress((void**)&B2p, g_B2);
    cudaGetSymbolAddress((void**)&dncp, g_dnc);
    cudaGetSymbolAddress((void**)&kpcp, g_kpc);

    wprep_kernel<<<(9 * 64 * 64 + 255) / 256, 256>>>(W1, W2, B1p, B2p);

    dim3 cgrid(HH, BB);
    conv_mma<16, 1><<<cgrid, 128>>>(mr, B1p, b1, g1, be1, mu1, v1, x1p);
    conv_mma<64, 0><<<cgrid, 128>>>(x1p, B2p, b2, g2, be2, mu2, v2, bfp);

    int n4 = BB * HH * WW * CC;
    softmax_mask_kernel<<<(n4 / 2 + 255) / 256, 256>>>(bfp, n4);

    int ncell = BB * 65 * 65 * CC;
    cell_kernel<<<(ncell + 255) / 256, 256>>>(bfp, pet, dncp, kpcp);

    int ncomb = BB * SN * SN * CC;
    combine_kernel<<<(ncomb + 255) / 256, 256>>>(dncp, kpcp, ratp);

    int ntot = BB * HH * WW * CC;
    out_kernel<<<(ntot + 255) / 256, 256>>>(bfp, ratp, outp, ntot);
}

// round 15
// speedup vs baseline: 1.0357x; 1.0357x over previous
#include <cuda_runtime.h>
#include <cuda_bf16.h>
#include <cstdint>

// Problem constants
#define BB 3
#define HH 256
#define WW 256
#define CC 16
#define NB 4
#define COUT 64
#define SN 64
#define EPS 1e-3f

// Scratch (__device__ globals: allocation-free rule)
__device__ float g_x1[BB * HH * WW * COUT];      // conv1 output (BN+ReLU, fp32)
__device__ float g_bf[BB * HH * WW * COUT];      // conv2 out -> softmax/mask in place
__device__ float g_ratio[BB * SN * SN * CC * NB];
__device__ float g_B1[9 * 64 * 16];              // W1 transposed [t][oc][ic], tf32-rounded
__device__ float g_B2[9 * 64 * 64];              // W2 transposed [t][oc][ic], tf32-rounded
__device__ float g_dnc[BB * 65 * 65 * CC * NB];  // 4x4 cell sums of b
__device__ float g_kpc[BB * 65 * 65 * CC * NB];  // 4x4 cell sums of pet*b

__device__ __forceinline__ uint32_t f2tf32(float f) {
    uint32_t r; asm("cvt.rna.tf32.f32 %0, %1;" : "=r"(r) : "f"(f)); return r;
}

__device__ __forceinline__ void mma_tf32(float& c0, float& c1, float& c2, float& c3,
                                         uint32_t a0, uint32_t a1, uint32_t a2, uint32_t a3,
                                         uint32_t b0, uint32_t b1) {
    asm volatile(
        "mma.sync.aligned.m16n8k8.row.col.f32.tf32.tf32.f32 "
        "{%0,%1,%2,%3}, {%4,%5,%6,%7}, {%8,%9}, {%0,%1,%2,%3};\n"
        : "+f"(c0), "+f"(c1), "+f"(c2), "+f"(c3)
        : "r"(a0), "r"(a1), "r"(a2), "r"(a3), "r"(b0), "r"(b1));
}

// ---------------------------------------------------------------------------
// Weight prep: W [3,3,CIN,64] (HWIO) -> B [9][64][CIN] tf32-rounded fp32
// ---------------------------------------------------------------------------
__global__ void wprep_kernel(const float* __restrict__ W1, const float* __restrict__ W2,
                             float* __restrict__ B1, float* __restrict__ B2)
{
    int i = blockIdx.x * blockDim.x + threadIdx.x;
    if (i < 9 * 64 * 16) {
        int ic = i & 15, oc = (i >> 4) & 63, t = i >> 10;
        uint32_t v = f2tf32(W1[(t * 16 + ic) * 64 + oc]);
        B1[(t * 64 + oc) * 16 + ic] = __uint_as_float(v);
    }
    if (i < 9 * 64 * 64) {
        int ic = i & 63, oc = (i >> 6) & 63, t = i >> 12;
        uint32_t v = f2tf32(W2[(t * 64 + ic) * 64 + oc]);
        B2[(t * 64 + oc) * 64 + ic] = __uint_as_float(v);
    }
}

// ---------------------------------------------------------------------------
// Implicit-GEMM 3x3 SAME conv via mma.sync tf32 + folded BN (round-4 shape,
// untouched). CTA = one image row: 256 px x 64 oc; 4 warps, M=64 x N=64.
// ---------------------------------------------------------------------------
#define ASTR 20
template <int CIN, int DO_RELU>
__global__ __launch_bounds__(128) void conv_mma(
    const float* __restrict__ in, const float* __restrict__ Bw,
    const float* __restrict__ bias, const float* __restrict__ gam,
    const float* __restrict__ bet, const float* __restrict__ mu,
    const float* __restrict__ var, float* __restrict__ out)
{
    __shared__ __align__(16) float s_a[258 * ASTR];
    __shared__ __align__(16) float s_b[3 * 64 * ASTR];
    __shared__ float s_sc[64], s_sh[64];

    const int tid  = threadIdx.x;
    const int lane = tid & 31;
    const int warp = tid >> 5;
    const int lg   = lane >> 2;
    const int lt   = lane & 3;
    const int wp0  = warp * 64;

    const int y  = blockIdx.x;
    const int bb = blockIdx.y;

    if (tid < 64) {
        float sc = gam[tid] * rsqrtf(var[tid] + EPS);
        s_sc[tid] = sc;
        s_sh[tid] = (bias[tid] - mu[tid]) * sc + bet[tid];
    }

    float acc[4][8][4];
#pragma unroll
    for (int mt = 0; mt < 4; ++mt)
#pragma unroll
        for (int n = 0; n < 8; ++n)
#pragma unroll
            for (int c = 0; c < 4; ++c) acc[mt][n][c] = 0.f;

    for (int ky = 0; ky < 3; ++ky) {
        const int gy = y + ky - 1;
        const bool row_ok = (unsigned)gy < (unsigned)HH;
        const float* rowp = in + ((size_t)(bb * HH + gy) * WW) * CIN;

        for (int ic0 = 0; ic0 < CIN; ic0 += 16) {
            __syncthreads();
            for (int idx = tid; idx < 258 * 4; idx += 128) {
                int c4 = idx & 3;
                int p  = idx >> 2;
                int gx = p - 1;
                uint4 v = make_uint4(0u, 0u, 0u, 0u);
                if (row_ok && (unsigned)gx < (unsigned)WW) {
                    float4 f = *(const float4*)(rowp + gx * CIN + ic0 + c4 * 4);
                    v.x = f2tf32(f.x); v.y = f2tf32(f.y);
                    v.z = f2tf32(f.z); v.w = f2tf32(f.w);
                }
                *(uint4*)&s_a[p * ASTR + c4 * 4] = v;
            }
            for (int idx = tid; idx < 3 * 64 * 4; idx += 128) {
                int c4  = idx & 3;
                int oc  = (idx >> 2) & 63;
                int tap = idx >> 8;
                float4 f = *(const float4*)(Bw + ((ky * 3 + tap) * 64 + oc) * CIN + ic0 + c4 * 4);
                *(float4*)&s_b[(tap * 64 + oc) * ASTR + c4 * 4] = f;
            }
            __syncthreads();

#pragma unroll
            for (int kx = 0; kx < 3; ++kx) {
#pragma unroll
                for (int g = 0; g < 2; ++g) {
                    const int icw = g * 8 + lt;
                    uint32_t b0[8], b1[8];
#pragma unroll
                    for (int n = 0; n < 8; ++n) {
                        const float* bp = &s_b[(kx * 64 + n * 8 + lg) * ASTR + icw];
                        b0[n] = __float_as_uint(bp[0]);
                        b1[n] = __float_as_uint(bp[4]);
                    }
#pragma unroll
                    for (int mt = 0; mt < 4; ++mt) {
                        const int r0 = wp0 + mt * 16 + kx + lg;
                        const float* ap0 = &s_a[r0 * ASTR + icw];
                        const float* ap1 = ap0 + 8 * ASTR;
                        uint32_t a0 = __float_as_uint(ap0[0]);
                        uint32_t a1 = __float_as_uint(ap1[0]);
                        uint32_t a2 = __float_as_uint(ap0[4]);
                        uint32_t a3 = __float_as_uint(ap1[4]);
#pragma unroll
                        for (int n = 0; n < 8; ++n)
                            mma_tf32(acc[mt][n][0], acc[mt][n][1], acc[mt][n][2], acc[mt][n][3],
                                     a0, a1, a2, a3, b0[n], b1[n]);
                    }
                }
            }
        }
    }

    // ---- epilogue: BN (+ReLU), store fp32 NHWC
    float* ob = out + ((size_t)(bb * HH + y) * WW) * COUT;
#pragma unroll
    for (int mt = 0; mt < 4; ++mt) {
        int prow = wp0 + mt * 16 + lg;
#pragma unroll
        for (int n = 0; n < 8; ++n) {
            int col = n * 8 + lt * 2;
            float sc0 = s_sc[col], sc1 = s_sc[col + 1];
            float sh0 = s_sh[col], sh1 = s_sh[col + 1];
            float v0 = acc[mt][n][0] * sc0 + sh0;
            float v1 = acc[mt][n][1] * sc1 + sh1;
            float v2 = acc[mt][n][2] * sc0 + sh0;
            float v3 = acc[mt][n][3] * sc1 + sh1;
            if (DO_RELU) {
                v0 = fmaxf(v0, 0.f); v1 = fmaxf(v1, 0.f);
                v2 = fmaxf(v2, 0.f); v3 = fmaxf(v3, 0.f);
            }
            *(float2*)(ob + (size_t)prow * COUT + col)       = make_float2(v0, v1);
            *(float2*)(ob + (size_t)(prow + 8) * COUT + col) = make_float2(v2, v3);
        }
    }
}

// ---------------------------------------------------------------------------
// Softmax over NB=4 + mask, in place (round-11 plain version: one float4
// per thread — measured fastest).
// ---------------------------------------------------------------------------
__global__ void softmax_mask_kernel(float* __restrict__ bf, int n4)
{
    int idx = blockIdx.x * blockDim.x + threadIdx.x;
    if (idx >= n4) return;
    float4 v = ((const float4*)bf)[idx];
    float mx = fmaxf(fmaxf(v.x, v.y), fmaxf(v.z, v.w));
    float ex = __expf(v.x - mx);
    float ey = __expf(v.y - mx);
    float ez = __expf(v.z - mx);
    float ew = __expf(v.w - mx);
    float inv = 1.f / (ex + ey + ez + ew);
    ex *= inv; ey *= inv; ez *= inv; ew *= inv;
    float4 o;
    o.x = ex > 1e-5f ? ex : 0.f;
    o.y = ey > 1e-5f ? ey : 0.f;
    o.z = ez > 1e-5f ? ez : 0.f;
    o.w = ew > 1e-5f ? ew : 0.f;
    ((float4*)bf)[idx] = o;
}

// ---------------------------------------------------------------------------
// Cell sums: non-overlapping 4x4 blocks over masked-softmax bf.
// Cell u covers gx in [4u-2, 4u+2), u = 0..64, edges clipped.
// ---------------------------------------------------------------------------
__global__ void cell_kernel(const float* __restrict__ bf, const float* __restrict__ pet,
                            float* __restrict__ dnc, float* __restrict__ kpc)
{
    int idx = blockIdx.x * blockDim.x + threadIdx.x;
    if (idx >= BB * 65 * 65 * CC) return;
    int cc = idx & 15;
    int t  = idx >> 4;
    int v  = t % 65;
    int t2 = t / 65;
    int u  = t2 % 65;
    int b  = t2 / 65;

    float4 dn = make_float4(0.f, 0.f, 0.f, 0.f);
    float4 kp = make_float4(0.f, 0.f, 0.f, 0.f);
    int gx0 = u * 4 - 2, gy0 = v * 4 - 2;
#pragma unroll
    for (int dx = 0; dx < 4; ++dx) {
        int gx = gx0 + dx;
        if ((unsigned)gx >= (unsigned)HH) continue;
#pragma unroll
        for (int dy = 0; dy < 4; ++dy) {
            int gy = gy0 + dy;
            if ((unsigned)gy >= (unsigned)WW) continue;
            int pix = (b * HH + gx) * WW + gy;
            float4 bv = *(const float4*)&bf[pix * COUT + cc * 4];
            float  pv = pet[pix * CC + cc];
            dn.x += bv.x; dn.y += bv.y; dn.z += bv.z; dn.w += bv.w;
            kp.x = fmaf(pv, bv.x, kp.x);
            kp.y = fmaf(pv, bv.y, kp.y);
            kp.z = fmaf(pv, bv.z, kp.z);
            kp.w = fmaf(pv, bv.w, kp.w);
        }
    }
    ((float4*)dnc)[idx] = dn;
    ((float4*)kpc)[idx] = kp;
}

// ---------------------------------------------------------------------------
// Combine 2x2 cells -> per-patch ratio with divide_no_nan.
// ---------------------------------------------------------------------------
__global__ void combine_kernel(const float* __restrict__ dnc, const float* __restrict__ kpc,
                               float* __restrict__ ratio)
{
    int idx = blockIdx.x * blockDim.x + threadIdx.x;
    if (idx >= BB * SN * SN * CC) return;
    int cc = idx & 15;
    int t  = idx >> 4;
    int m  = t & 63;
    int t2 = t >> 6;
    int n  = t2 & 63;
    int b  = t2 >> 6;

    float4 dn = make_float4(0.f, 0.f, 0.f, 0.f);
    float4 kp = make_float4(0.f, 0.f, 0.f, 0.f);
#pragma unroll
    for (int du = 0; du < 2; ++du)
#pragma unroll
        for (int dv = 0; dv < 2; ++dv) {
            int ci = (((b * 65 + n + du) * 65) + m + dv) * CC + cc;
            float4 d = ((const float4*)dnc)[ci];
            float4 k = ((const float4*)kpc)[ci];
            dn.x += d.x; dn.y += d.y; dn.z += d.z; dn.w += d.w;
            kp.x += k.x; kp.y += k.y; kp.z += k.z; kp.w += k.w;
        }
    float4 r;
    r.x = dn.x != 0.f ? kp.x / dn.x : 0.f;
    r.y = dn.y != 0.f ? kp.y / dn.y : 0.f;
    r.z = dn.z != 0.f ? kp.z / dn.z : 0.f;
    r.w = dn.w != 0.f ? kp.w / dn.w : 0.f;
    ((float4*)ratio)[idx] = r;
}

// ---------------------------------------------------------------------------
// Final gather over masked-softmax bf. Interior (2<=X<254, 2<=Y<254): all
// four (i,j) terms hit the SAME bf pixel (X,Y) -> one bf load, dot with the
// SUM of the four ratio vectors. Boundary: general wrapped path.
// ---------------------------------------------------------------------------
__global__ void out_kernel(const float* __restrict__ bf,
                           const float* __restrict__ ratio,
                           float* __restrict__ out, int ntot)
{
    int idx = blockIdx.x * blockDim.x + threadIdx.x;
    if (idx >= ntot) return;
    int cc  = idx & 15;
    int pix = idx >> 4;
    int Y = pix & 255;
    int t = pix >> 8;
    int X = t & 255;
    int b = t >> 8;

    float s;
    if (X >= 2 && X < 254 && Y >= 2 && Y < 254) {
        int n0 = ((X + 2) >> 3) * 2;
        int n1 = ((X - 2) >> 3) * 2 + 1;
        int m0 = ((Y + 2) >> 3) * 2;
        int m1 = ((Y - 2) >> 3) * 2 + 1;
        const float4* rb = (const float4*)ratio;
        int base = (b * SN) * SN * CC;
        float4 r00 = rb[base + (n0 * SN + m0) * CC + cc];
        float4 r01 = rb[base + (n0 * SN + m1) * CC + cc];
        float4 r10 = rb[base + (n1 * SN + m0) * CC + cc];
        float4 r11 = rb[base + (n1 * SN + m1) * CC + cc];
        float4 rs;
        rs.x = (r00.x + r01.x) + (r10.x + r11.x);
        rs.y = (r00.y + r01.y) + (r10.y + r11.y);
        rs.z = (r00.z + r01.z) + (r10.z + r11.z);
        rs.w = (r00.w + r01.w) + (r10.w + r11.w);
        float4 bv = *(const float4*)&bf[((b * HH + X) * WW + Y) * COUT + cc * 4];
        s = bv.x * rs.x + bv.y * rs.y + bv.z * rs.z + bv.w * rs.w;
    } else {
        s = 0.f;
#pragma unroll
        for (int j = 0; j < 2; ++j) {
            int Yp = (Y - (j ? 2 : -2)) & 255;
            int m  = (Yp >> 3) * 2 + j;
            int gy = Yp + 4 * j - 2;
#pragma unroll
            for (int i = 0; i < 2; ++i) {
                int Xp = (X - (i ? 2 : -2)) & 255;
                int n  = (Xp >> 3) * 2 + i;
                int gx = Xp + 4 * i - 2;
                if ((unsigned)gx < (unsigned)HH && (unsigned)gy < (unsigned)WW) {
                    int pp = (b * HH + gx) * WW + gy;
                    float4 bv = *(const float4*)&bf[pp * COUT + cc * 4];
                    float4 rv = *(const float4*)&ratio[(((b * SN + n) * SN + m) * CC + cc) * 4];
                    s += bv.x * rv.x + bv.y * rv.y + bv.z * rv.z + bv.w * rv.w;
                }
            }
        }
    }
    out[idx] = s * 0.25f;
}

// ---------------------------------------------------------------------------
extern "C" void kernel_launch(void* const* d_in, const int* in_sizes, int n_in,
                              void* d_out, int out_size)
{
    const float* mr  = (const float*)d_in[0];
    const float* pet = (const float*)d_in[1];
    const float* W1  = (const float*)d_in[2];
    const float* b1  = (const float*)d_in[3];
    const float* g1  = (const float*)d_in[4];
    const float* be1 = (const float*)d_in[5];
    const float* mu1 = (const float*)d_in[6];
    const float* v1  = (const float*)d_in[7];
    const float* W2  = (const float*)d_in[8];
    const float* b2  = (const float*)d_in[9];
    const float* g2  = (const float*)d_in[10];
    const float* be2 = (const float*)d_in[11];
    const float* mu2 = (const float*)d_in[12];
    const float* v2  = (const float*)d_in[13];
    float* outp = (float*)d_out;

    float *x1p, *bfp, *ratp, *B1p, *B2p, *dncp, *kpcp;
    cudaGetSymbolAddress((void**)&x1p, g_x1);
    cudaGetSymbolAddress((void**)&bfp, g_bf);
    cudaGetSymbolAddress((void**)&ratp, g_ratio);
    cudaGetSymbolAddress((void**)&B1p, g_B1);
    cudaGetSymbolAddress((void**)&B2p, g_B2);
    cudaGetSymbolAddress((void**)&dncp, g_dnc);
    cudaGetSymbolAddress((void**)&kpcp, g_kpc);

    wprep_kernel<<<(9 * 64 * 64 + 255) / 256, 256>>>(W1, W2, B1p, B2p);

    dim3 cgrid(HH, BB);
    conv_mma<16, 1><<<cgrid, 128>>>(mr, B1p, b1, g1, be1, mu1, v1, x1p);
    conv_mma<64, 0><<<cgrid, 128>>>(x1p, B2p, b2, g2, be2, mu2, v2, bfp);

    int n4 = BB * HH * WW * CC;
    softmax_mask_kernel<<<(n4 + 255) / 256, 256>>>(bfp, n4);

    int ncell = BB * 65 * 65 * CC;
    cell_kernel<<<(ncell + 255) / 256, 256>>>(bfp, pet, dncp, kpcp);

    int ncomb = BB * SN * SN * CC;
    combine_kernel<<<(ncomb + 255) / 256, 256>>>(dncp, kpcp, ratp);

    int ntot = BB * HH * WW * CC;
    out_kernel<<<(ntot + 255) / 256, 256>>>(bfp, ratp, outp, ntot);
}